// round 5
// baseline (speedup 1.0000x reference)
#include <cuda_runtime.h>
#include <cstdint>
#include <math.h>

// Problem constants
#define BB 4
#define NN 2048
#define DD 512
#define HH 8
#define HD 64
#define NC 2048
#define RR (BB*NN)

// Scratch (device globals; no allocation allowed)
__device__ float g_xn[(size_t)RR * DD];   // layernorm(x); reused for o_input
__device__ float g_mm[(size_t)RR * NC];   // silu(xn @ uvqk): [u | v | q | k]
__device__ float g_at[(size_t)RR * DD];   // attention output

__device__ __forceinline__ float silu_f(float v) {
    return v / (1.0f + __expf(-v));
}

__device__ __forceinline__ uint32_t smem_u32(const void* p) {
    uint32_t a;
    asm("{ .reg .u64 t; cvta.to.shared.u64 t, %1; cvt.u32.u64 %0, t; }"
        : "=r"(a) : "l"(p));
    return a;
}

__device__ __forceinline__ void ldmA(uint32_t* a, uint32_t addr) {
    asm volatile("ldmatrix.sync.aligned.m8n8.x4.shared.b16 {%0,%1,%2,%3}, [%4];"
                 : "=r"(a[0]), "=r"(a[1]), "=r"(a[2]), "=r"(a[3]) : "r"(addr));
}

__device__ __forceinline__ void mma_tf32(float* d, const uint32_t* a,
                                         uint32_t b0, uint32_t b1) {
    asm volatile(
        "mma.sync.aligned.m16n8k8.row.col.f32.tf32.tf32.f32 "
        "{%0,%1,%2,%3},{%4,%5,%6,%7},{%8,%9},{%0,%1,%2,%3};"
        : "+f"(d[0]), "+f"(d[1]), "+f"(d[2]), "+f"(d[3])
        : "r"(a[0]), "r"(a[1]), "r"(a[2]), "r"(a[3]), "r"(b0), "r"(b1));
}

__device__ __forceinline__ void cp16(uint32_t dst, const void* src) {
    asm volatile("cp.async.cg.shared.global [%0], [%1], 16;" :: "r"(dst), "l"(src));
}
#define CP_COMMIT() asm volatile("cp.async.commit_group;" ::: "memory")
#define CP_WAIT(n)  asm volatile("cp.async.wait_group %0;" :: "n"(n) : "memory")

__device__ __forceinline__ uint32_t ldm_off(int lane, int sa_floats) {
    int r = (lane & 7) + ((lane >> 3) & 1) * 8;
    int c16 = (lane >> 4);
    return (uint32_t)(r * sa_floats * 4 + c16 * 16);
}

// ---------------------------------------------------------------------------
// LayerNorm kernels (known-good)
// ---------------------------------------------------------------------------
__global__ void ln_kernel(const float* __restrict__ x) {
    int row = blockIdx.x;
    int t = threadIdx.x;
    float4 v = ((const float4*)(x + (size_t)row * DD))[t];
    float s  = v.x + v.y + v.z + v.w;
    float s2 = v.x*v.x + v.y*v.y + v.z*v.z + v.w*v.w;
#pragma unroll
    for (int o = 16; o > 0; o >>= 1) {
        s  += __shfl_xor_sync(0xffffffffu, s,  o);
        s2 += __shfl_xor_sync(0xffffffffu, s2, o);
    }
    __shared__ float sh[8];
    if ((t & 31) == 0) { sh[t >> 5] = s; sh[4 + (t >> 5)] = s2; }
    __syncthreads();
    s  = sh[0] + sh[1] + sh[2] + sh[3];
    s2 = sh[4] + sh[5] + sh[6] + sh[7];
    float mu  = s * (1.0f / DD);
    float var = fmaxf(s2 * (1.0f / DD) - mu * mu, 0.0f);
    float r   = rsqrtf(var + 1e-6f);
    float4 o;
    o.x = (v.x - mu) * r; o.y = (v.y - mu) * r;
    o.z = (v.z - mu) * r; o.w = (v.w - mu) * r;
    ((float4*)(g_xn + (size_t)row * DD))[t] = o;
}

__global__ void gated_ln_kernel() {
    int row = blockIdx.x;
    int t = threadIdx.x;
    float4 v = ((const float4*)(g_at + (size_t)row * DD))[t];
    float s  = v.x + v.y + v.z + v.w;
    float s2 = v.x*v.x + v.y*v.y + v.z*v.z + v.w*v.w;
#pragma unroll
    for (int o = 16; o > 0; o >>= 1) {
        s  += __shfl_xor_sync(0xffffffffu, s,  o);
        s2 += __shfl_xor_sync(0xffffffffu, s2, o);
    }
    __shared__ float sh[8];
    if ((t & 31) == 0) { sh[t >> 5] = s; sh[4 + (t >> 5)] = s2; }
    __syncthreads();
    s  = sh[0] + sh[1] + sh[2] + sh[3];
    s2 = sh[4] + sh[5] + sh[6] + sh[7];
    float mu  = s * (1.0f / DD);
    float var = fmaxf(s2 * (1.0f / DD) - mu * mu, 0.0f);
    float r   = rsqrtf(var + 1e-6f);
    float4 u = ((const float4*)(g_mm + (size_t)row * NC))[t];
    float4 o;
    o.x = u.x * (v.x - mu) * r; o.y = u.y * (v.y - mu) * r;
    o.z = u.z * (v.z - mu) * r; o.w = u.w * (v.w - mu) * r;
    ((float4*)(g_xn + (size_t)row * DD))[t] = o;
}

// ---------------------------------------------------------------------------
// tf32 mma.sync GEMM (unchanged, known-good)
// ---------------------------------------------------------------------------
#define SA  36
#define ASB (128 * SA * 4)
#define SB0 136
#define BSB0 (32 * SB0 * 4)
#define SB1 36
#define BSB1 (128 * SB1 * 4)
#define GSMEM (2 * ASB + 2 * BSB1)

template <int MODE>
__global__ __launch_bounds__(256)
void gemm_mma(const float* __restrict__ A, const float* __restrict__ Bm,
              float* __restrict__ C, const float* __restrict__ bias,
              const float* __restrict__ xres, int Nn, int K) {
    extern __shared__ char smem[];
    const int BSB = (MODE == 0) ? BSB0 : BSB1;
    char* sB = smem + 2 * ASB;
    uint32_t sAu = smem_u32(smem);
    uint32_t sBu = smem_u32(sB);

    int tid = threadIdx.x;
    int wid = tid >> 5, lane = tid & 31;
    int m0 = blockIdx.y * 128, n0 = blockIdx.x * 128;
    int wm = (wid & 1) * 64;
    int wn = (wid >> 1) * 32;

    float acc[4][4][4];
#pragma unroll
    for (int i = 0; i < 4; i++)
#pragma unroll
        for (int j = 0; j < 4; j++)
#pragma unroll
            for (int r = 0; r < 4; r++) acc[i][j][r] = 0.0f;

    const int NCH = K / 32;
    uint32_t aoff = ldm_off(lane, SA);

    auto stageA = [&](int c, int s) {
#pragma unroll
        for (int i = 0; i < 4; i++) {
            int idx = tid + i * 256;
            int row = idx >> 3, seg = idx & 7;
            cp16(sAu + s * ASB + (row * SA + seg * 4) * 4,
                 A + (size_t)(m0 + row) * K + c * 32 + seg * 4);
        }
    };
    auto stageB = [&](int c, int s) {
        if (MODE == 0) {
#pragma unroll
            for (int i = 0; i < 4; i++) {
                int idx = tid + i * 256;
                int row = idx >> 5, seg = idx & 31;
                cp16(sBu + s * BSB + (row * SB0 + seg * 4) * 4,
                     Bm + (size_t)(c * 32 + row) * Nn + n0 + seg * 4);
            }
        } else {
#pragma unroll
            for (int i = 0; i < 4; i++) {
                int idx = tid + i * 256;
                int row = idx >> 3, seg = idx & 7;
                cp16(sBu + s * BSB + (row * SB1 + seg * 4) * 4,
                     Bm + (size_t)(n0 + row) * K + c * 32 + seg * 4);
            }
        }
    };

    stageA(0, 0); stageB(0, 0); CP_COMMIT();

    for (int c = 0; c < NCH; c++) {
        int s = c & 1;
        if (c + 1 < NCH) {
            stageA(c + 1, s ^ 1); stageB(c + 1, s ^ 1); CP_COMMIT();
            CP_WAIT(1);
        } else {
            CP_WAIT(0);
        }
        __syncthreads();

        const float* Bsf = (const float*)(sB + s * BSB);
#pragma unroll
        for (int ks = 0; ks < 4; ks++) {
            uint32_t bf[4][2];
#pragma unroll
            for (int in = 0; in < 4; in++) {
                int nn = wn + in * 8 + lane / 4;
                int kk = ks * 8 + (lane & 3);
                if (MODE == 0) {
                    bf[in][0] = __float_as_uint(Bsf[kk * SB0 + nn]);
                    bf[in][1] = __float_as_uint(Bsf[(kk + 4) * SB0 + nn]);
                } else {
                    bf[in][0] = __float_as_uint(Bsf[nn * SB1 + kk]);
                    bf[in][1] = __float_as_uint(Bsf[nn * SB1 + kk + 4]);
                }
            }
#pragma unroll
            for (int im = 0; im < 4; im++) {
                uint32_t a[4];
                ldmA(a, sAu + s * ASB + (uint32_t)(((wm + im * 16) * SA + ks * 8) * 4) + aoff);
#pragma unroll
                for (int in = 0; in < 4; in++)
                    mma_tf32(acc[im][in], a, bf[in][0], bf[in][1]);
            }
        }
        __syncthreads();
    }

    int er = lane >> 2, ec = (lane & 3) * 2;
#pragma unroll
    for (int im = 0; im < 4; im++) {
#pragma unroll
        for (int in = 0; in < 4; in++) {
            int row = m0 + wm + im * 16 + er;
            int col = n0 + wn + in * 8 + ec;
#pragma unroll
            for (int h = 0; h < 2; h++) {
                float v0 = acc[im][in][2 * h + 0];
                float v1 = acc[im][in][2 * h + 1];
                int rr = row + 8 * h;
                if (MODE == 0) {
                    float2 o; o.x = silu_f(v0); o.y = silu_f(v1);
                    *(float2*)(C + (size_t)rr * Nn + col) = o;
                } else {
                    float2 bi = *(const float2*)(bias + col);
                    float2 xr = *(const float2*)(xres + (size_t)rr * Nn + col);
                    float2 o; o.x = v0 + bi.x + xr.x; o.y = v1 + bi.y + xr.y;
                    *(float2*)(C + (size_t)rr * Nn + col) = o;
                }
            }
        }
    }
}

// ---------------------------------------------------------------------------
// Fused causal silu-attention, round 5:
// 64x64 tiles, 128 threads = 4 warps, each warp owns 16 q-rows x ALL 64 kv
// cols. S stays in registers; accumulator->A-fragment conversion is done with
// intra-quad shuffles (no S smem, no third sync). cp.async double-buffered
// K/V. Smem = Q + 2K + 2V = 87040 B -> 2 CTAs/SM.
// ---------------------------------------------------------------------------
#define SAT 68
#define ATILE (64 * SAT * 4)           // 17408
#define AOFF_K ATILE                   // Ks[2]
#define AOFF_V (3 * ATILE)             // Vs[2]
#define ASMEM  (5 * ATILE)             // 87040

__global__ __launch_bounds__(128)
void attn_mma() {
    extern __shared__ char smem[];
    float* Qs = (float*)smem;
    uint32_t sbase = smem_u32(smem);

    int qt = blockIdx.x, h = blockIdx.y, b = blockIdx.z;
    int tid = threadIdx.x;
    int wid = tid >> 5, lane = tid & 31;
    const int qcol = 1024 + h * HD;
    const int kcol = 1536 + h * HD;
    const int vcol = 512 + h * HD;
    uint32_t aoff = ldm_off(lane, SAT);

    // Load Q tile (64 x 64)
#pragma unroll
    for (int i = 0; i < 8; i++) {
        int idx = tid + i * 128;           // 1024 float4 slots
        int row = idx >> 4, seg = idx & 15;
        float4 v = *(const float4*)(g_mm + (size_t)(b * NN + qt * 64 + row) * NC + qcol + seg * 4);
        *(float4*)(Qs + row * SAT + seg * 4) = v;
    }

    auto stageKV = [&](int kt, int s) {
        uint32_t kd = sbase + AOFF_K + s * ATILE;
        uint32_t vd = sbase + AOFF_V + s * ATILE;
#pragma unroll
        for (int i = 0; i < 8; i++) {
            int idx = tid + i * 128;       // 1024 segs each
            int row = idx >> 4, seg = idx & 15;
            size_t gb = (size_t)(b * NN + kt * 64 + row) * NC;
            uint32_t so = (uint32_t)((row * SAT + seg * 4) * 4);
            cp16(kd + so, g_mm + gb + kcol + seg * 4);
            cp16(vd + so, g_mm + gb + vcol + seg * 4);
        }
    };

    float oacc[8][4];
#pragma unroll
    for (int j = 0; j < 8; j++)
#pragma unroll
        for (int r = 0; r < 4; r++) oacc[j][r] = 0.0f;

    const float inv_n = 1.0f / (float)NN;
    int er = lane >> 2, ec = (lane & 3) * 2;
    int q = lane & 3;
    int s0 = (lane & ~3) | (q >> 1);
    int s1 = s0 + 2;
    const int nkt = qt + 1;

    stageKV(0, 0); CP_COMMIT();

    for (int kt = 0; kt < nkt; kt++) {
        int s = kt & 1;
        __syncthreads();   // all warps done reading buffer s^1 (iter kt-1)
        if (kt + 1 < nkt) {
            stageKV(kt + 1, s ^ 1); CP_COMMIT();
            CP_WAIT(1);
        } else {
            CP_WAIT(0);
        }
        __syncthreads();   // buffer s data visible to all warps

        const float* Ksf = (const float*)(smem + AOFF_K + s * ATILE);
        const float* Vsf = (const float*)(smem + AOFF_V + s * ATILE);

        // Phase 1: S strip = Q[wid*16..+16] @ K^T  (full 64 kv cols per warp)
        float sacc[8][4];
#pragma unroll
        for (int j = 0; j < 8; j++)
#pragma unroll
            for (int r = 0; r < 4; r++) sacc[j][r] = 0.0f;
#pragma unroll
        for (int ks = 0; ks < 8; ks++) {
            uint32_t a[4];
            ldmA(a, sbase + (uint32_t)(((wid * 16) * SAT + ks * 8) * 4) + aoff);
#pragma unroll
            for (int in = 0; in < 8; in++) {
                int nn = in * 8 + (lane >> 2);
                int kk = ks * 8 + (lane & 3);
                uint32_t b0 = __float_as_uint(Ksf[nn * SAT + kk]);
                uint32_t b1 = __float_as_uint(Ksf[nn * SAT + kk + 4]);
                mma_tf32(sacc[in], a, b0, b1);
            }
        }

        // silu/N + causal mask (registers only)
        bool diag = (kt == qt);
        int ig0 = qt * 64 + wid * 16 + er;
        int ig1 = ig0 + 8;
#pragma unroll
        for (int in = 0; in < 8; in++) {
            int jg = kt * 64 + in * 8 + ec;
            float v0 = silu_f(sacc[in][0]) * inv_n;
            float v1 = silu_f(sacc[in][1]) * inv_n;
            float v2 = silu_f(sacc[in][2]) * inv_n;
            float v3 = silu_f(sacc[in][3]) * inv_n;
            if (diag) {
                if (jg > ig0)     v0 = 0.0f;
                if (jg + 1 > ig0) v1 = 0.0f;
                if (jg > ig1)     v2 = 0.0f;
                if (jg + 1 > ig1) v3 = 0.0f;
            }
            sacc[in][0] = v0; sacc[in][1] = v1;
            sacc[in][2] = v2; sacc[in][3] = v3;
        }

        // Phase 2: O += S @ V. A-fragments built from sacc via intra-quad
        // shuffles: target col q (and 4+q) sourced from quad-lane q>>1 (and
        // 2+(q>>1)), element q&1.
#pragma unroll
        for (int ks = 0; ks < 8; ks++) {
            float e0a = __shfl_sync(0xffffffffu, sacc[ks][0], s0);
            float e0b = __shfl_sync(0xffffffffu, sacc[ks][1], s0);
            float e1a = __shfl_sync(0xffffffffu, sacc[ks][2], s0);
            float e1b = __shfl_sync(0xffffffffu, sacc[ks][3], s0);
            float e2a = __shfl_sync(0xffffffffu, sacc[ks][0], s1);
            float e2b = __shfl_sync(0xffffffffu, sacc[ks][1], s1);
            float e3a = __shfl_sync(0xffffffffu, sacc[ks][2], s1);
            float e3b = __shfl_sync(0xffffffffu, sacc[ks][3], s1);
            uint32_t af[4];
            af[0] = __float_as_uint((q & 1) ? e0b : e0a);
            af[1] = __float_as_uint((q & 1) ? e1b : e1a);
            af[2] = __float_as_uint((q & 1) ? e2b : e2a);
            af[3] = __float_as_uint((q & 1) ? e3b : e3a);
#pragma unroll
            for (int in = 0; in < 8; in++) {
                int nn = in * 8 + (lane >> 2);
                int kk = ks * 8 + (lane & 3);
                uint32_t b0 = __float_as_uint(Vsf[kk * SAT + nn]);
                uint32_t b1 = __float_as_uint(Vsf[(kk + 4) * SAT + nn]);
                mma_tf32(oacc[in], af, b0, b1);
            }
        }
    }

    // Write O strip (16 rows x 64 cols per warp)
#pragma unroll
    for (int in = 0; in < 8; in++) {
        int n0r = qt * 64 + wid * 16 + er;
        int j = h * HD + in * 8 + ec;
        float2 o0; o0.x = oacc[in][0]; o0.y = oacc[in][1];
        float2 o1; o1.x = oacc[in][2]; o1.y = oacc[in][3];
        *(float2*)(g_at + (size_t)(b * NN + n0r) * DD + j) = o0;
        *(float2*)(g_at + (size_t)(b * NN + n0r + 8) * DD + j) = o1;
    }
}

// ---------------------------------------------------------------------------
extern "C" void kernel_launch(void* const* d_in, const int* in_sizes, int n_in,
                              void* d_out, int out_size) {
    const float* x    = (const float*)d_in[0];
    const float* uvqk = (const float*)d_in[2];
    const float* ow   = (const float*)d_in[3];
    const float* ob   = (const float*)d_in[4];
    float* out = (float*)d_out;

    void *pxn, *pmm;
    cudaGetSymbolAddress(&pxn, g_xn);
    cudaGetSymbolAddress(&pmm, g_mm);

    cudaFuncSetAttribute(gemm_mma<0>, cudaFuncAttributeMaxDynamicSharedMemorySize, GSMEM);
    cudaFuncSetAttribute(gemm_mma<1>, cudaFuncAttributeMaxDynamicSharedMemorySize, GSMEM);
    cudaFuncSetAttribute(attn_mma, cudaFuncAttributeMaxDynamicSharedMemorySize, ASMEM);

    // 1. xn = layernorm(x)
    ln_kernel<<<RR, 128>>>(x);
    // 2. mm = silu(xn @ uvqk)  [8192 x 2048, K=512]
    gemm_mma<0><<<dim3(NC / 128, RR / 128), 256, GSMEM>>>(
        (const float*)pxn, uvqk, (float*)pmm, nullptr, nullptr, NC, DD);
    // 3. attention (64-row q-tiles, 1024 blocks)
    attn_mma<<<dim3(NN / 64, HH, BB), 128, ASMEM>>>();
    // 4. o_input = u * layernorm(attn) -> g_xn
    gated_ln_kernel<<<RR, 128>>>();
    // 5. out = o_input @ o_weight^T + bias + x  [8192 x 512, K=512]
    gemm_mma<1><<<dim3(DD / 128, RR / 128), 256, GSMEM>>>(
        (const float*)pxn, ow, out, ob, x, DD, DD);
}

// round 6
// speedup vs baseline: 1.2437x; 1.2437x over previous
#include <cuda_runtime.h>
#include <cstdint>
#include <math.h>

// Problem constants
#define BB 4
#define NN 2048
#define DD 512
#define HH 8
#define HD 64
#define NC 2048
#define RR (BB*NN)

// Scratch (device globals; no allocation allowed)
__device__ float g_xn[(size_t)RR * DD];   // layernorm(x); reused for o_input
__device__ float g_mm[(size_t)RR * NC];   // silu(xn @ uvqk): [u | v | q | k]
__device__ float g_at[(size_t)RR * DD];   // attention output

__device__ __forceinline__ float silu_f(float v) {
    return v / (1.0f + __expf(-v));
}

__device__ __forceinline__ uint32_t smem_u32(const void* p) {
    uint32_t a;
    asm("{ .reg .u64 t; cvta.to.shared.u64 t, %1; cvt.u32.u64 %0, t; }"
        : "=r"(a) : "l"(p));
    return a;
}

__device__ __forceinline__ void ldmA(uint32_t* a, uint32_t addr) {
    asm volatile("ldmatrix.sync.aligned.m8n8.x4.shared.b16 {%0,%1,%2,%3}, [%4];"
                 : "=r"(a[0]), "=r"(a[1]), "=r"(a[2]), "=r"(a[3]) : "r"(addr));
}

__device__ __forceinline__ void mma_tf32(float* d, const uint32_t* a,
                                         uint32_t b0, uint32_t b1) {
    asm volatile(
        "mma.sync.aligned.m16n8k8.row.col.f32.tf32.tf32.f32 "
        "{%0,%1,%2,%3},{%4,%5,%6,%7},{%8,%9},{%0,%1,%2,%3};"
        : "+f"(d[0]), "+f"(d[1]), "+f"(d[2]), "+f"(d[3])
        : "r"(a[0]), "r"(a[1]), "r"(a[2]), "r"(a[3]), "r"(b0), "r"(b1));
}

__device__ __forceinline__ void cp16(uint32_t dst, const void* src) {
    asm volatile("cp.async.cg.shared.global [%0], [%1], 16;" :: "r"(dst), "l"(src));
}
#define CP_COMMIT() asm volatile("cp.async.commit_group;" ::: "memory")
#define CP_WAIT(n)  asm volatile("cp.async.wait_group %0;" :: "n"(n) : "memory")

__device__ __forceinline__ uint32_t ldm_off(int lane, int sa_floats) {
    int r = (lane & 7) + ((lane >> 3) & 1) * 8;
    int c16 = (lane >> 4);
    return (uint32_t)(r * sa_floats * 4 + c16 * 16);
}

// ---------------------------------------------------------------------------
// LayerNorm kernels (known-good)
// ---------------------------------------------------------------------------
__global__ void ln_kernel(const float* __restrict__ x) {
    int row = blockIdx.x;
    int t = threadIdx.x;
    float4 v = ((const float4*)(x + (size_t)row * DD))[t];
    float s  = v.x + v.y + v.z + v.w;
    float s2 = v.x*v.x + v.y*v.y + v.z*v.z + v.w*v.w;
#pragma unroll
    for (int o = 16; o > 0; o >>= 1) {
        s  += __shfl_xor_sync(0xffffffffu, s,  o);
        s2 += __shfl_xor_sync(0xffffffffu, s2, o);
    }
    __shared__ float sh[8];
    if ((t & 31) == 0) { sh[t >> 5] = s; sh[4 + (t >> 5)] = s2; }
    __syncthreads();
    s  = sh[0] + sh[1] + sh[2] + sh[3];
    s2 = sh[4] + sh[5] + sh[6] + sh[7];
    float mu  = s * (1.0f / DD);
    float var = fmaxf(s2 * (1.0f / DD) - mu * mu, 0.0f);
    float r   = rsqrtf(var + 1e-6f);
    float4 o;
    o.x = (v.x - mu) * r; o.y = (v.y - mu) * r;
    o.z = (v.z - mu) * r; o.w = (v.w - mu) * r;
    ((float4*)(g_xn + (size_t)row * DD))[t] = o;
}

__global__ void gated_ln_kernel() {
    int row = blockIdx.x;
    int t = threadIdx.x;
    float4 v = ((const float4*)(g_at + (size_t)row * DD))[t];
    float s  = v.x + v.y + v.z + v.w;
    float s2 = v.x*v.x + v.y*v.y + v.z*v.z + v.w*v.w;
#pragma unroll
    for (int o = 16; o > 0; o >>= 1) {
        s  += __shfl_xor_sync(0xffffffffu, s,  o);
        s2 += __shfl_xor_sync(0xffffffffu, s2, o);
    }
    __shared__ float sh[8];
    if ((t & 31) == 0) { sh[t >> 5] = s; sh[4 + (t >> 5)] = s2; }
    __syncthreads();
    s  = sh[0] + sh[1] + sh[2] + sh[3];
    s2 = sh[4] + sh[5] + sh[6] + sh[7];
    float mu  = s * (1.0f / DD);
    float var = fmaxf(s2 * (1.0f / DD) - mu * mu, 0.0f);
    float r   = rsqrtf(var + 1e-6f);
    float4 u = ((const float4*)(g_mm + (size_t)row * NC))[t];
    float4 o;
    o.x = u.x * (v.x - mu) * r; o.y = u.y * (v.y - mu) * r;
    o.z = u.z * (v.z - mu) * r; o.w = u.w * (v.w - mu) * r;
    ((float4*)(g_xn + (size_t)row * DD))[t] = o;
}

// ---------------------------------------------------------------------------
// tf32 mma.sync GEMM (unchanged, known-good)
// ---------------------------------------------------------------------------
#define SA  36
#define ASB (128 * SA * 4)
#define SB0 136
#define BSB0 (32 * SB0 * 4)
#define SB1 36
#define BSB1 (128 * SB1 * 4)
#define GSMEM (2 * ASB + 2 * BSB1)

template <int MODE>
__global__ __launch_bounds__(256)
void gemm_mma(const float* __restrict__ A, const float* __restrict__ Bm,
              float* __restrict__ C, const float* __restrict__ bias,
              const float* __restrict__ xres, int Nn, int K) {
    extern __shared__ char smem[];
    const int BSB = (MODE == 0) ? BSB0 : BSB1;
    char* sB = smem + 2 * ASB;
    uint32_t sAu = smem_u32(smem);
    uint32_t sBu = smem_u32(sB);

    int tid = threadIdx.x;
    int wid = tid >> 5, lane = tid & 31;
    int m0 = blockIdx.y * 128, n0 = blockIdx.x * 128;
    int wm = (wid & 1) * 64;
    int wn = (wid >> 1) * 32;

    float acc[4][4][4];
#pragma unroll
    for (int i = 0; i < 4; i++)
#pragma unroll
        for (int j = 0; j < 4; j++)
#pragma unroll
            for (int r = 0; r < 4; r++) acc[i][j][r] = 0.0f;

    const int NCH = K / 32;
    uint32_t aoff = ldm_off(lane, SA);

    auto stageA = [&](int c, int s) {
#pragma unroll
        for (int i = 0; i < 4; i++) {
            int idx = tid + i * 256;
            int row = idx >> 3, seg = idx & 7;
            cp16(sAu + s * ASB + (row * SA + seg * 4) * 4,
                 A + (size_t)(m0 + row) * K + c * 32 + seg * 4);
        }
    };
    auto stageB = [&](int c, int s) {
        if (MODE == 0) {
#pragma unroll
            for (int i = 0; i < 4; i++) {
                int idx = tid + i * 256;
                int row = idx >> 5, seg = idx & 31;
                cp16(sBu + s * BSB + (row * SB0 + seg * 4) * 4,
                     Bm + (size_t)(c * 32 + row) * Nn + n0 + seg * 4);
            }
        } else {
#pragma unroll
            for (int i = 0; i < 4; i++) {
                int idx = tid + i * 256;
                int row = idx >> 3, seg = idx & 7;
                cp16(sBu + s * BSB + (row * SB1 + seg * 4) * 4,
                     Bm + (size_t)(n0 + row) * K + c * 32 + seg * 4);
            }
        }
    };

    stageA(0, 0); stageB(0, 0); CP_COMMIT();

    for (int c = 0; c < NCH; c++) {
        int s = c & 1;
        if (c + 1 < NCH) {
            stageA(c + 1, s ^ 1); stageB(c + 1, s ^ 1); CP_COMMIT();
            CP_WAIT(1);
        } else {
            CP_WAIT(0);
        }
        __syncthreads();

        const float* Bsf = (const float*)(sB + s * BSB);
#pragma unroll
        for (int ks = 0; ks < 4; ks++) {
            uint32_t bf[4][2];
#pragma unroll
            for (int in = 0; in < 4; in++) {
                int nn = wn + in * 8 + lane / 4;
                int kk = ks * 8 + (lane & 3);
                if (MODE == 0) {
                    bf[in][0] = __float_as_uint(Bsf[kk * SB0 + nn]);
                    bf[in][1] = __float_as_uint(Bsf[(kk + 4) * SB0 + nn]);
                } else {
                    bf[in][0] = __float_as_uint(Bsf[nn * SB1 + kk]);
                    bf[in][1] = __float_as_uint(Bsf[nn * SB1 + kk + 4]);
                }
            }
#pragma unroll
            for (int im = 0; im < 4; im++) {
                uint32_t a[4];
                ldmA(a, sAu + s * ASB + (uint32_t)(((wm + im * 16) * SA + ks * 8) * 4) + aoff);
#pragma unroll
                for (int in = 0; in < 4; in++)
                    mma_tf32(acc[im][in], a, bf[in][0], bf[in][1]);
            }
        }
        __syncthreads();
    }

    int er = lane >> 2, ec = (lane & 3) * 2;
#pragma unroll
    for (int im = 0; im < 4; im++) {
#pragma unroll
        for (int in = 0; in < 4; in++) {
            int row = m0 + wm + im * 16 + er;
            int col = n0 + wn + in * 8 + ec;
#pragma unroll
            for (int h = 0; h < 2; h++) {
                float v0 = acc[im][in][2 * h + 0];
                float v1 = acc[im][in][2 * h + 1];
                int rr = row + 8 * h;
                if (MODE == 0) {
                    float2 o; o.x = silu_f(v0); o.y = silu_f(v1);
                    *(float2*)(C + (size_t)rr * Nn + col) = o;
                } else {
                    float2 bi = *(const float2*)(bias + col);
                    float2 xr = *(const float2*)(xres + (size_t)rr * Nn + col);
                    float2 o; o.x = v0 + bi.x + xr.x; o.y = v1 + bi.y + xr.y;
                    *(float2*)(C + (size_t)rr * Nn + col) = o;
                }
            }
        }
    }
}

// ---------------------------------------------------------------------------
// Fused causal silu-attention, round 6 = round 3 shape + cp.async pipeline.
// 64x64 tiles, 256 threads = 8 warps (2m x 4n), warp tile 32x16.
// K/V double-buffered via cp.async; next tile staged right after the top
// sync so the loads overlap both mma phases. 2 syncs/iter.
// Smem: Qs | Ks[2] | Vs[2] | Ss = 6*17408 = 104448 B -> 2 CTAs/SM.
// ---------------------------------------------------------------------------
#define SAT 68
#define ATILE (64 * SAT * 4)           // 17408
#define AOFF_K ATILE
#define AOFF_V (3 * ATILE)
#define AOFF_S (5 * ATILE)
#define ASMEM  (6 * ATILE)             // 104448

__global__ __launch_bounds__(256)
void attn_mma() {
    extern __shared__ char smem[];
    float* Qs = (float*)smem;
    float* Ss = (float*)(smem + AOFF_S);
    uint32_t sbase = smem_u32(smem);
    uint32_t Qsu = sbase;
    uint32_t Ssu = sbase + AOFF_S;

    int qt = blockIdx.x, h = blockIdx.y, b = blockIdx.z;
    int tid = threadIdx.x;
    int wid = tid >> 5, lane = tid & 31;
    int wm = (wid & 1) * 32;           // 2 warps over 64 rows
    int wn = (wid >> 1) * 16;          // 4 warps over 64 cols
    const int qcol = 1024 + h * HD;
    const int kcol = 1536 + h * HD;
    const int vcol = 512 + h * HD;
    uint32_t aoff = ldm_off(lane, SAT);

    // Load Q tile (64 x 64)
#pragma unroll
    for (int i = 0; i < 4; i++) {
        int idx = tid + i * 256;           // 1024 float4 slots
        int row = idx >> 4, seg = idx & 15;
        float4 v = *(const float4*)(g_mm + (size_t)(b * NN + qt * 64 + row) * NC + qcol + seg * 4);
        *(float4*)(Qs + row * SAT + seg * 4) = v;
    }

    auto stageKV = [&](int kt, int s) {
        uint32_t kd = sbase + AOFF_K + s * ATILE;
        uint32_t vd = sbase + AOFF_V + s * ATILE;
#pragma unroll
        for (int i = 0; i < 4; i++) {
            int idx = tid + i * 256;       // 1024 segs each
            int row = idx >> 4, seg = idx & 15;
            size_t gb = (size_t)(b * NN + kt * 64 + row) * NC;
            uint32_t so = (uint32_t)((row * SAT + seg * 4) * 4);
            cp16(kd + so, g_mm + gb + kcol + seg * 4);
            cp16(vd + so, g_mm + gb + vcol + seg * 4);
        }
    };

    float oacc[2][2][4];
#pragma unroll
    for (int i = 0; i < 2; i++)
#pragma unroll
        for (int j = 0; j < 2; j++)
#pragma unroll
            for (int r = 0; r < 4; r++) oacc[i][j][r] = 0.0f;

    const float inv_n = 1.0f / (float)NN;
    int er = lane >> 2, ec = (lane & 3) * 2;
    const int nkt = qt + 1;

    stageKV(0, 0); CP_COMMIT();

    for (int kt = 0; kt < nkt; kt++) {
        int s = kt & 1;
        CP_WAIT(0);
        __syncthreads();   // tile kt visible; all warps past phase2 of kt-1

        if (kt + 1 < nkt) { stageKV(kt + 1, s ^ 1); CP_COMMIT(); }

        const float* Ksf = (const float*)(smem + AOFF_K + s * ATILE);
        const float* Vsf = (const float*)(smem + AOFF_V + s * ATILE);

        // Phase 1: S = Q @ K^T  (b0 = Ks[n_seq][k_d])
        float sacc[2][2][4];
#pragma unroll
        for (int i = 0; i < 2; i++)
#pragma unroll
            for (int j = 0; j < 2; j++)
#pragma unroll
                for (int r = 0; r < 4; r++) sacc[i][j][r] = 0.0f;
#pragma unroll
        for (int ks = 0; ks < 8; ks++) {
            uint32_t bf[2][2];
#pragma unroll
            for (int in = 0; in < 2; in++) {
                int nn = wn + in * 8 + lane / 4;
                int kk = ks * 8 + (lane & 3);
                bf[in][0] = __float_as_uint(Ksf[nn * SAT + kk]);
                bf[in][1] = __float_as_uint(Ksf[nn * SAT + kk + 4]);
            }
#pragma unroll
            for (int im = 0; im < 2; im++) {
                uint32_t a[4];
                ldmA(a, Qsu + (uint32_t)(((wm + im * 16) * SAT + ks * 8) * 4) + aoff);
#pragma unroll
                for (int in = 0; in < 2; in++)
                    mma_tf32(sacc[im][in], a, bf[in][0], bf[in][1]);
            }
        }

        // silu/N + causal mask -> Ss
        bool diag = (kt == qt);
#pragma unroll
        for (int im = 0; im < 2; im++) {
#pragma unroll
            for (int in = 0; in < 2; in++) {
#pragma unroll
                for (int hh = 0; hh < 2; hh++) {
                    int i = wm + im * 16 + er + 8 * hh;
                    int j = wn + in * 8 + ec;
                    float v0 = silu_f(sacc[im][in][2 * hh + 0]) * inv_n;
                    float v1 = silu_f(sacc[im][in][2 * hh + 1]) * inv_n;
                    if (diag) {
                        if (j > i) v0 = 0.0f;
                        if (j + 1 > i) v1 = 0.0f;
                    }
                    float2 o; o.x = v0; o.y = v1;
                    *(float2*)(Ss + i * SAT + j) = o;
                }
            }
        }
        __syncthreads();   // Ss visible

        // Phase 2: O += S @ V  (b0 = Vs[k_seq][n_d])
#pragma unroll
        for (int ks = 0; ks < 8; ks++) {
            uint32_t bf[2][2];
#pragma unroll
            for (int in = 0; in < 2; in++) {
                int nn = wn + in * 8 + lane / 4;
                int kk = ks * 8 + (lane & 3);
                bf[in][0] = __float_as_uint(Vsf[kk * SAT + nn]);
                bf[in][1] = __float_as_uint(Vsf[(kk + 4) * SAT + nn]);
            }
#pragma unroll
            for (int im = 0; im < 2; im++) {
                uint32_t a[4];
                ldmA(a, Ssu + (uint32_t)(((wm + im * 16) * SAT + ks * 8) * 4) + aoff);
#pragma unroll
                for (int in = 0; in < 2; in++)
                    mma_tf32(oacc[im][in], a, bf[in][0], bf[in][1]);
            }
        }
    }

    // Write O tile
#pragma unroll
    for (int im = 0; im < 2; im++) {
#pragma unroll
        for (int in = 0; in < 2; in++) {
#pragma unroll
            for (int hh = 0; hh < 2; hh++) {
                int n = qt * 64 + wm + im * 16 + er + 8 * hh;
                int j = h * HD + wn + in * 8 + ec;
                float2 o;
                o.x = oacc[im][in][2 * hh + 0];
                o.y = oacc[im][in][2 * hh + 1];
                *(float2*)(g_at + (size_t)(b * NN + n) * DD + j) = o;
            }
        }
    }
}

// ---------------------------------------------------------------------------
extern "C" void kernel_launch(void* const* d_in, const int* in_sizes, int n_in,
                              void* d_out, int out_size) {
    const float* x    = (const float*)d_in[0];
    const float* uvqk = (const float*)d_in[2];
    const float* ow   = (const float*)d_in[3];
    const float* ob   = (const float*)d_in[4];
    float* out = (float*)d_out;

    void *pxn, *pmm;
    cudaGetSymbolAddress(&pxn, g_xn);
    cudaGetSymbolAddress(&pmm, g_mm);

    cudaFuncSetAttribute(gemm_mma<0>, cudaFuncAttributeMaxDynamicSharedMemorySize, GSMEM);
    cudaFuncSetAttribute(gemm_mma<1>, cudaFuncAttributeMaxDynamicSharedMemorySize, GSMEM);
    cudaFuncSetAttribute(attn_mma, cudaFuncAttributeMaxDynamicSharedMemorySize, ASMEM);

    // 1. xn = layernorm(x)
    ln_kernel<<<RR, 128>>>(x);
    // 2. mm = silu(xn @ uvqk)  [8192 x 2048, K=512]
    gemm_mma<0><<<dim3(NC / 128, RR / 128), 256, GSMEM>>>(
        (const float*)pxn, uvqk, (float*)pmm, nullptr, nullptr, NC, DD);
    // 3. attention (64-row q-tiles, 1024 blocks)
    attn_mma<<<dim3(NN / 64, HH, BB), 256, ASMEM>>>();
    // 4. o_input = u * layernorm(attn) -> g_xn
    gated_ln_kernel<<<RR, 128>>>();
    // 5. out = o_input @ o_weight^T + bias + x  [8192 x 512, K=512]
    gemm_mma<1><<<dim3(DD / 128, RR / 128), 256, GSMEM>>>(
        (const float*)pxn, ow, out, ob, x, DD, DD);
}

// round 7
// speedup vs baseline: 2.1503x; 1.7290x over previous
#include <cuda_runtime.h>
#include <cuda_fp16.h>
#include <cstdint>
#include <math.h>

// Problem constants
#define BB 4
#define NN 2048
#define DD 512
#define HH 8
#define HD 64
#define NC 2048
#define RR (BB*NN)

// Scratch (device globals; no allocation allowed)
__device__ __half g_xnh[(size_t)RR * DD];   // half: layernorm(x); later o_input
__device__ __half g_mmh[(size_t)RR * NC];   // half: silu(xn @ uvqk) [u|v|q|k]
__device__ __half g_wh [(size_t)NC * DD];   // half: uvqk transposed [n][k]
__device__ __half g_owh[(size_t)DD * DD];   // half: o_weight [n][k]
__device__ float  g_at [(size_t)RR * DD];   // fp32 attention output

__device__ __forceinline__ float silu_f(float v) {
    return v / (1.0f + __expf(-v));
}

__device__ __forceinline__ uint32_t smem_u32(const void* p) {
    uint32_t a;
    asm("{ .reg .u64 t; cvta.to.shared.u64 t, %1; cvt.u32.u64 %0, t; }"
        : "=r"(a) : "l"(p));
    return a;
}

__device__ __forceinline__ void ldmA(uint32_t* a, uint32_t addr) {
    asm volatile("ldmatrix.sync.aligned.m8n8.x4.shared.b16 {%0,%1,%2,%3}, [%4];"
                 : "=r"(a[0]), "=r"(a[1]), "=r"(a[2]), "=r"(a[3]) : "r"(addr));
}

__device__ __forceinline__ void ldmT(uint32_t* a, uint32_t addr) {
    asm volatile("ldmatrix.sync.aligned.m8n8.x4.trans.shared.b16 {%0,%1,%2,%3}, [%4];"
                 : "=r"(a[0]), "=r"(a[1]), "=r"(a[2]), "=r"(a[3]) : "r"(addr));
}

// fp16 mma, fp32 accumulate: D += A(16x16) * B(16x8)
__device__ __forceinline__ void mma_f16(float* d, const uint32_t* a,
                                        uint32_t b0, uint32_t b1) {
    asm volatile(
        "mma.sync.aligned.m16n8k16.row.col.f32.f16.f16.f32 "
        "{%0,%1,%2,%3},{%4,%5,%6,%7},{%8,%9},{%0,%1,%2,%3};"
        : "+f"(d[0]), "+f"(d[1]), "+f"(d[2]), "+f"(d[3])
        : "r"(a[0]), "r"(a[1]), "r"(a[2]), "r"(a[3]), "r"(b0), "r"(b1));
}

__device__ __forceinline__ void cp16(uint32_t dst, const void* src) {
    asm volatile("cp.async.cg.shared.global [%0], [%1], 16;" :: "r"(dst), "l"(src));
}
#define CP_COMMIT() asm volatile("cp.async.commit_group;" ::: "memory")
#define CP_WAIT(n)  asm volatile("cp.async.wait_group %0;" :: "n"(n) : "memory")

// ldmatrix-x4 per-lane byte offset for a 16x16-half A block, stride in halfs
__device__ __forceinline__ uint32_t ldm_off_h(int lane, int stride_halfs) {
    int r = (lane & 7) + ((lane >> 3) & 1) * 8;
    int c16 = (lane >> 4);                 // 0/1 -> k0 / k8 (16B)
    return (uint32_t)(r * stride_halfs * 2 + c16 * 16);
}

// ---------------------------------------------------------------------------
// LayerNorm: fp32 math, half output
// ---------------------------------------------------------------------------
__global__ void ln_kernel(const float* __restrict__ x) {
    int row = blockIdx.x;
    int t = threadIdx.x;
    float4 v = ((const float4*)(x + (size_t)row * DD))[t];
    float s  = v.x + v.y + v.z + v.w;
    float s2 = v.x*v.x + v.y*v.y + v.z*v.z + v.w*v.w;
#pragma unroll
    for (int o = 16; o > 0; o >>= 1) {
        s  += __shfl_xor_sync(0xffffffffu, s,  o);
        s2 += __shfl_xor_sync(0xffffffffu, s2, o);
    }
    __shared__ float sh[8];
    if ((t & 31) == 0) { sh[t >> 5] = s; sh[4 + (t >> 5)] = s2; }
    __syncthreads();
    s  = sh[0] + sh[1] + sh[2] + sh[3];
    s2 = sh[4] + sh[5] + sh[6] + sh[7];
    float mu  = s * (1.0f / DD);
    float var = fmaxf(s2 * (1.0f / DD) - mu * mu, 0.0f);
    float r   = rsqrtf(var + 1e-6f);
    __half2 h0 = __floats2half2_rn((v.x - mu) * r, (v.y - mu) * r);
    __half2 h1 = __floats2half2_rn((v.z - mu) * r, (v.w - mu) * r);
    ((__half2*)(g_xnh + (size_t)row * DD))[2 * t]     = h0;
    ((__half2*)(g_xnh + (size_t)row * DD))[2 * t + 1] = h1;
}

// Gated LN: o_input = u * layernorm(attn), half output into g_xnh
__global__ void gated_ln_kernel() {
    int row = blockIdx.x;
    int t = threadIdx.x;
    float4 v = ((const float4*)(g_at + (size_t)row * DD))[t];
    float s  = v.x + v.y + v.z + v.w;
    float s2 = v.x*v.x + v.y*v.y + v.z*v.z + v.w*v.w;
#pragma unroll
    for (int o = 16; o > 0; o >>= 1) {
        s  += __shfl_xor_sync(0xffffffffu, s,  o);
        s2 += __shfl_xor_sync(0xffffffffu, s2, o);
    }
    __shared__ float sh[8];
    if ((t & 31) == 0) { sh[t >> 5] = s; sh[4 + (t >> 5)] = s2; }
    __syncthreads();
    s  = sh[0] + sh[1] + sh[2] + sh[3];
    s2 = sh[4] + sh[5] + sh[6] + sh[7];
    float mu  = s * (1.0f / DD);
    float var = fmaxf(s2 * (1.0f / DD) - mu * mu, 0.0f);
    float r   = rsqrtf(var + 1e-6f);
    __half2 u01 = ((const __half2*)(g_mmh + (size_t)row * NC))[2 * t];
    __half2 u23 = ((const __half2*)(g_mmh + (size_t)row * NC))[2 * t + 1];
    float2 u0 = __half22float2(u01), u1 = __half22float2(u23);
    __half2 h0 = __floats2half2_rn(u0.x * (v.x - mu) * r, u0.y * (v.y - mu) * r);
    __half2 h1 = __floats2half2_rn(u1.x * (v.z - mu) * r, u1.y * (v.w - mu) * r);
    ((__half2*)(g_xnh + (size_t)row * DD))[2 * t]     = h0;
    ((__half2*)(g_xnh + (size_t)row * DD))[2 * t + 1] = h1;
}

// ---------------------------------------------------------------------------
// Weight converts (once per launch)
// uvqk [D=512][NC=2048] fp32 -> g_wh [NC][D] half (transposed)
// ---------------------------------------------------------------------------
__global__ void cvt_w_t(const float* __restrict__ W) {
    __shared__ float tbuf[32][33];
    int lx = threadIdx.x & 31, ly = threadIdx.x >> 5;  // 32x8
    int bx = blockIdx.x, by = blockIdx.y;              // (64, 16)
    int col = bx * 32 + lx;                            // 0..2047
#pragma unroll
    for (int i = 0; i < 32; i += 8)
        tbuf[ly + i][lx] = W[(size_t)(by * 32 + ly + i) * NC + col];
    __syncthreads();
    int ok = by * 32 + lx;                             // 0..511 (k)
#pragma unroll
    for (int i = 0; i < 32; i += 8)
        g_wh[(size_t)(bx * 32 + ly + i) * DD + ok] = __float2half_rn(tbuf[lx][ly + i]);
}

// o_weight [512][512] fp32 -> g_owh half (same layout [n][k])
__global__ void cvt_ow(const float* __restrict__ W) {
    int i = blockIdx.x * 256 + threadIdx.x;            // 1024 blocks? grid=256
    float4 v = ((const float4*)W)[i];
    __half2 h0 = __floats2half2_rn(v.x, v.y);
    __half2 h1 = __floats2half2_rn(v.z, v.w);
    ((__half2*)g_owh)[2 * i]     = h0;
    ((__half2*)g_owh)[2 * i + 1] = h1;
}

// ---------------------------------------------------------------------------
// fp16 mma GEMM. Block tile 128x128, BK=64 halfs, 8 warps (2m x 4n),
// warp tile 64x32, cp.async double buffer. A [m][k] half, B [n][k] half.
// MODE 0: C = silu(A @ B^T) -> half to g_mmh   (B = g_wh)
// MODE 1: C = A @ B^T + bias + xres -> fp32     (B = g_owh)
// ---------------------------------------------------------------------------
#define SAH   72                          // row stride in halfs (144 B)
#define ASBH  (128 * SAH * 2)             // 18432 bytes per stage
#define GSMEMH (4 * ASBH)                 // A[2] + B[2] = 73728

template <int MODE>
__global__ __launch_bounds__(256)
void gemm_h(const __half* __restrict__ A, const __half* __restrict__ Bm,
            __half* __restrict__ Ch, float* __restrict__ Cf,
            const float* __restrict__ bias, const float* __restrict__ xres,
            int Nn, int K) {
    extern __shared__ char smem[];
    uint32_t sAu = smem_u32(smem);
    uint32_t sBu = sAu + 2 * ASBH;

    int tid = threadIdx.x;
    int wid = tid >> 5, lane = tid & 31;
    int m0 = blockIdx.y * 128, n0 = blockIdx.x * 128;
    int wm = (wid & 1) * 64;
    int wn = (wid >> 1) * 32;

    float acc[4][4][4];
#pragma unroll
    for (int i = 0; i < 4; i++)
#pragma unroll
        for (int j = 0; j < 4; j++)
#pragma unroll
            for (int r = 0; r < 4; r++) acc[i][j][r] = 0.0f;

    const int NCH = K / 64;
    uint32_t aoff = ldm_off_h(lane, SAH);

    auto stageA = [&](int c, int s) {
#pragma unroll
        for (int i = 0; i < 4; i++) {
            int idx = tid + i * 256;          // 1024 segs (128 rows x 8)
            int row = idx >> 3, seg = idx & 7;
            cp16(sAu + s * ASBH + (row * SAH + seg * 8) * 2,
                 A + (size_t)(m0 + row) * K + c * 64 + seg * 8);
        }
    };
    auto stageB = [&](int c, int s) {
#pragma unroll
        for (int i = 0; i < 4; i++) {
            int idx = tid + i * 256;
            int row = idx >> 3, seg = idx & 7;
            cp16(sBu + s * ASBH + (row * SAH + seg * 8) * 2,
                 Bm + (size_t)(n0 + row) * K + c * 64 + seg * 8);
        }
    };

    stageA(0, 0); stageB(0, 0); CP_COMMIT();

    for (int c = 0; c < NCH; c++) {
        int s = c & 1;
        if (c + 1 < NCH) {
            stageA(c + 1, s ^ 1); stageB(c + 1, s ^ 1); CP_COMMIT();
            CP_WAIT(1);
        } else {
            CP_WAIT(0);
        }
        __syncthreads();

        const __half* Bsf = (const __half*)(smem + 2 * ASBH + s * ASBH);
#pragma unroll
        for (int ks = 0; ks < 4; ks++) {      // 4 k16 steps per 64-chunk
            uint32_t bf[4][2];
#pragma unroll
            for (int in = 0; in < 4; in++) {
                int nn = wn + in * 8 + (lane >> 2);
                int kk = ks * 16 + (lane & 3) * 2;
                bf[in][0] = *(const uint32_t*)&Bsf[nn * SAH + kk];
                bf[in][1] = *(const uint32_t*)&Bsf[nn * SAH + kk + 8];
            }
#pragma unroll
            for (int im = 0; im < 4; im++) {
                uint32_t a[4];
                ldmA(a, sAu + s * ASBH + (uint32_t)((wm + im * 16) * SAH * 2 + ks * 32) + aoff);
#pragma unroll
                for (int in = 0; in < 4; in++)
                    mma_f16(acc[im][in], a, bf[in][0], bf[in][1]);
            }
        }
        __syncthreads();
    }

    int er = lane >> 2, ec = (lane & 3) * 2;
#pragma unroll
    for (int im = 0; im < 4; im++) {
#pragma unroll
        for (int in = 0; in < 4; in++) {
            int row = m0 + wm + im * 16 + er;
            int col = n0 + wn + in * 8 + ec;
#pragma unroll
            for (int h = 0; h < 2; h++) {
                float v0 = acc[im][in][2 * h + 0];
                float v1 = acc[im][in][2 * h + 1];
                int rr = row + 8 * h;
                if (MODE == 0) {
                    __half2 o = __floats2half2_rn(silu_f(v0), silu_f(v1));
                    *(__half2*)(Ch + (size_t)rr * Nn + col) = o;
                } else {
                    float2 bi = *(const float2*)(bias + col);
                    float2 xr = *(const float2*)(xres + (size_t)rr * Nn + col);
                    float2 o; o.x = v0 + bi.x + xr.x; o.y = v1 + bi.y + xr.y;
                    *(float2*)(Cf + (size_t)rr * Nn + col) = o;
                }
            }
        }
    }
}

// ---------------------------------------------------------------------------
// Fused causal silu-attention, fp16 mma (round-3 shape + cp.async pipeline).
// 64x64 tiles, 256 threads = 8 warps (2m x 4n), warp tile 32x16.
// Q/S A-frags via ldmatrix; K B-frags scalar half2 (k-pairs contiguous);
// V B-frags via ldmatrix.x4.trans from natural [seq][d] tile.
// inv_n applied to O at the end (linear). Smem 54 KB.
// ---------------------------------------------------------------------------
#define SATH  72
#define ATILEH (64 * SATH * 2)            // 9216
#define HOFF_K ATILEH
#define HOFF_V (3 * ATILEH)
#define HOFF_S (5 * ATILEH)
#define ASMEMH (6 * ATILEH)               // 55296

__global__ __launch_bounds__(256)
void attn_mma() {
    extern __shared__ char smem[];
    __half* Ss = (__half*)(smem + HOFF_S);
    uint32_t sbase = smem_u32(smem);
    uint32_t Qsu = sbase;
    uint32_t Ssu = sbase + HOFF_S;

    int qt = blockIdx.x, h = blockIdx.y, b = blockIdx.z;
    int tid = threadIdx.x;
    int wid = tid >> 5, lane = tid & 31;
    int wm = (wid & 1) * 32;
    int wn = (wid >> 1) * 16;
    const int qcol = 1024 + h * HD;
    const int kcol = 1536 + h * HD;
    const int vcol = 512 + h * HD;
    uint32_t aoff = ldm_off_h(lane, SATH);

    // V ldmatrix.x4.trans per-lane address pieces
    int tl = lane & 7;
    int tmi = lane >> 3;                   // 0..3 matrix id
    int tkr = (tmi & 1) * 8 + tl;          // k-row within 16
    int tnc = (tmi >> 1) * 8;              // n-col block 0/8

    // Stage Q (with first K/V group)
    auto stageQ = [&]() {
#pragma unroll
        for (int i = 0; i < 2; i++) {
            int idx = tid + i * 256;       // 512 segs (64 rows x 8)
            int row = idx >> 3, seg = idx & 7;
            cp16(Qsu + (row * SATH + seg * 8) * 2,
                 g_mmh + (size_t)(b * NN + qt * 64 + row) * NC + qcol + seg * 8);
        }
    };
    auto stageKV = [&](int kt, int s) {
        uint32_t kd = sbase + HOFF_K + s * ATILEH;
        uint32_t vd = sbase + HOFF_V + s * ATILEH;
#pragma unroll
        for (int i = 0; i < 2; i++) {
            int idx = tid + i * 256;       // 512 segs each
            int row = idx >> 3, seg = idx & 7;
            size_t gb = (size_t)(b * NN + kt * 64 + row) * NC;
            uint32_t so = (uint32_t)((row * SATH + seg * 8) * 2);
            cp16(kd + so, g_mmh + gb + kcol + seg * 8);
            cp16(vd + so, g_mmh + gb + vcol + seg * 8);
        }
    };

    float oacc[2][2][4];
#pragma unroll
    for (int i = 0; i < 2; i++)
#pragma unroll
        for (int j = 0; j < 2; j++)
#pragma unroll
            for (int r = 0; r < 4; r++) oacc[i][j][r] = 0.0f;

    const float inv_n = 1.0f / (float)NN;
    int er = lane >> 2, ec = (lane & 3) * 2;
    const int nkt = qt + 1;

    stageQ(); stageKV(0, 0); CP_COMMIT();

    for (int kt = 0; kt < nkt; kt++) {
        int s = kt & 1;
        CP_WAIT(0);
        __syncthreads();   // tile kt visible; all warps past phase2 of kt-1

        if (kt + 1 < nkt) { stageKV(kt + 1, s ^ 1); CP_COMMIT(); }

        const __half* Ksf = (const __half*)(smem + HOFF_K + s * ATILEH);
        uint32_t Vsu = sbase + HOFF_V + s * ATILEH;

        // Phase 1: S = Q @ K^T (K B-frags: k-pairs along d contiguous)
        float sacc[2][2][4];
#pragma unroll
        for (int i = 0; i < 2; i++)
#pragma unroll
            for (int j = 0; j < 2; j++)
#pragma unroll
                for (int r = 0; r < 4; r++) sacc[i][j][r] = 0.0f;
#pragma unroll
        for (int ks = 0; ks < 4; ks++) {   // 4 k16 steps over d=64
            uint32_t bf[2][2];
#pragma unroll
            for (int in = 0; in < 2; in++) {
                int nn = wn + in * 8 + (lane >> 2);
                int kk = ks * 16 + (lane & 3) * 2;
                bf[in][0] = *(const uint32_t*)&Ksf[nn * SATH + kk];
                bf[in][1] = *(const uint32_t*)&Ksf[nn * SATH + kk + 8];
            }
#pragma unroll
            for (int im = 0; im < 2; im++) {
                uint32_t a[4];
                ldmA(a, Qsu + (uint32_t)((wm + im * 16) * SATH * 2 + ks * 32) + aoff);
#pragma unroll
                for (int in = 0; in < 2; in++)
                    mma_f16(sacc[im][in], a, bf[in][0], bf[in][1]);
            }
        }

        // silu + causal mask -> Ss (half). inv_n deferred to O epilogue.
        bool diag = (kt == qt);
#pragma unroll
        for (int im = 0; im < 2; im++) {
#pragma unroll
            for (int in = 0; in < 2; in++) {
#pragma unroll
                for (int hh = 0; hh < 2; hh++) {
                    int i = wm + im * 16 + er + 8 * hh;
                    int j = wn + in * 8 + ec;
                    float v0 = silu_f(sacc[im][in][2 * hh + 0]);
                    float v1 = silu_f(sacc[im][in][2 * hh + 1]);
                    if (diag) {
                        if (j > i) v0 = 0.0f;
                        if (j + 1 > i) v1 = 0.0f;
                    }
                    *(__half2*)(Ss + i * SATH + j) = __floats2half2_rn(v0, v1);
                }
            }
        }
        __syncthreads();   // Ss visible

        // Phase 2: O += S @ V  (V B-frags via ldmatrix.x4.trans, both n-blocks)
#pragma unroll
        for (int ks = 0; ks < 4; ks++) {
            uint32_t bv[4];
            ldmT(bv, Vsu + (uint32_t)(((ks * 16 + tkr) * SATH + wn + tnc) * 2));
#pragma unroll
            for (int im = 0; im < 2; im++) {
                uint32_t a[4];
                ldmA(a, Ssu + (uint32_t)((wm + im * 16) * SATH * 2 + ks * 32) + aoff);
                mma_f16(oacc[im][0], a, bv[0], bv[1]);
                mma_f16(oacc[im][1], a, bv[2], bv[3]);
            }
        }
    }

    // Write O tile (scaled by 1/N)
#pragma unroll
    for (int im = 0; im < 2; im++) {
#pragma unroll
        for (int in = 0; in < 2; in++) {
#pragma unroll
            for (int hh = 0; hh < 2; hh++) {
                int n = qt * 64 + wm + im * 16 + er + 8 * hh;
                int j = h * HD + wn + in * 8 + ec;
                float2 o;
                o.x = oacc[im][in][2 * hh + 0] * inv_n;
                o.y = oacc[im][in][2 * hh + 1] * inv_n;
                *(float2*)(g_at + (size_t)(b * NN + n) * DD + j) = o;
            }
        }
    }
}

// ---------------------------------------------------------------------------
extern "C" void kernel_launch(void* const* d_in, const int* in_sizes, int n_in,
                              void* d_out, int out_size) {
    const float* x    = (const float*)d_in[0];
    const float* uvqk = (const float*)d_in[2];
    const float* ow   = (const float*)d_in[3];
    const float* ob   = (const float*)d_in[4];
    float* out = (float*)d_out;

    void *pxnh, *pmmh, *pwh, *powh;
    cudaGetSymbolAddress(&pxnh, g_xnh);
    cudaGetSymbolAddress(&pmmh, g_mmh);
    cudaGetSymbolAddress(&pwh,  g_wh);
    cudaGetSymbolAddress(&powh, g_owh);

    cudaFuncSetAttribute(gemm_h<0>, cudaFuncAttributeMaxDynamicSharedMemorySize, GSMEMH);
    cudaFuncSetAttribute(gemm_h<1>, cudaFuncAttributeMaxDynamicSharedMemorySize, GSMEMH);
    cudaFuncSetAttribute(attn_mma, cudaFuncAttributeMaxDynamicSharedMemorySize, ASMEMH);

    // 0. weight converts (independent of ln)
    cvt_w_t<<<dim3(NC / 32, DD / 32), 256>>>(uvqk);
    cvt_ow<<<DD * DD / 1024, 256>>>(ow);
    // 1. xn = layernorm(x) -> half
    ln_kernel<<<RR, 128>>>(x);
    // 2. mm = silu(xn @ uvqk) -> half  [8192 x 2048, K=512]
    gemm_h<0><<<dim3(NC / 128, RR / 128), 256, GSMEMH>>>(
        (const __half*)pxnh, (const __half*)pwh, (__half*)pmmh, nullptr,
        nullptr, nullptr, NC, DD);
    // 3. attention
    attn_mma<<<dim3(NN / 64, HH, BB), 256, ASMEMH>>>();
    // 4. o_input = u * layernorm(attn) -> half (g_xnh reused)
    gated_ln_kernel<<<RR, 128>>>();
    // 5. out = o_input @ o_weight^T + bias + x -> fp32
    gemm_h<1><<<dim3(DD / 128, RR / 128), 256, GSMEMH>>>(
        (const __half*)pxnh, (const __half*)powh, nullptr, out, ob, x, DD, DD);
}

// round 8
// speedup vs baseline: 2.1983x; 1.0223x over previous
#include <cuda_runtime.h>
#include <cuda_fp16.h>
#include <cstdint>
#include <math.h>

// Problem constants
#define BB 4
#define NN 2048
#define DD 512
#define HH 8
#define HD 64
#define NC 2048
#define RR (BB*NN)

// Scratch (device globals; no allocation allowed)
__device__ __half g_xnh[(size_t)RR * DD];   // half: layernorm(x); later o_input
__device__ __half g_mmh[(size_t)RR * NC];   // half: silu(xn @ uvqk) [u|v|q|k]
__device__ __half g_wh [(size_t)NC * DD];   // half: uvqk transposed [n][k]
__device__ __half g_owh[(size_t)DD * DD];   // half: o_weight [n][k]
__device__ float  g_at [(size_t)RR * DD];   // fp32 attention output

__device__ __forceinline__ float silu_f(float v) {
    return v / (1.0f + __expf(-v));
}

__device__ __forceinline__ uint32_t smem_u32(const void* p) {
    uint32_t a;
    asm("{ .reg .u64 t; cvta.to.shared.u64 t, %1; cvt.u32.u64 %0, t; }"
        : "=r"(a) : "l"(p));
    return a;
}

__device__ __forceinline__ void ldmA(uint32_t* a, uint32_t addr) {
    asm volatile("ldmatrix.sync.aligned.m8n8.x4.shared.b16 {%0,%1,%2,%3}, [%4];"
                 : "=r"(a[0]), "=r"(a[1]), "=r"(a[2]), "=r"(a[3]) : "r"(addr));
}

__device__ __forceinline__ void ldmT(uint32_t* a, uint32_t addr) {
    asm volatile("ldmatrix.sync.aligned.m8n8.x4.trans.shared.b16 {%0,%1,%2,%3}, [%4];"
                 : "=r"(a[0]), "=r"(a[1]), "=r"(a[2]), "=r"(a[3]) : "r"(addr));
}

// fp16 mma, fp32 accumulate: D += A(16x16) * B(16x8)
__device__ __forceinline__ void mma_f16(float* d, const uint32_t* a,
                                        uint32_t b0, uint32_t b1) {
    asm volatile(
        "mma.sync.aligned.m16n8k16.row.col.f32.f16.f16.f32 "
        "{%0,%1,%2,%3},{%4,%5,%6,%7},{%8,%9},{%0,%1,%2,%3};"
        : "+f"(d[0]), "+f"(d[1]), "+f"(d[2]), "+f"(d[3])
        : "r"(a[0]), "r"(a[1]), "r"(a[2]), "r"(a[3]), "r"(b0), "r"(b1));
}

__device__ __forceinline__ void cp16(uint32_t dst, const void* src) {
    asm volatile("cp.async.cg.shared.global [%0], [%1], 16;" :: "r"(dst), "l"(src));
}
#define CP_COMMIT() asm volatile("cp.async.commit_group;" ::: "memory")
#define CP_WAIT(n)  asm volatile("cp.async.wait_group %0;" :: "n"(n) : "memory")

// ldmatrix-x4 per-lane byte offset for a 16x16-half A block, stride in halfs
__device__ __forceinline__ uint32_t ldm_off_h(int lane, int stride_halfs) {
    int r = (lane & 7) + ((lane >> 3) & 1) * 8;
    int c16 = (lane >> 4);                 // 0/1 -> k0 / k8 (16B)
    return (uint32_t)(r * stride_halfs * 2 + c16 * 16);
}

// ldmatrix-x4 per-lane byte offset for B (K-major [n][k]): loads 2 n-frags x k16.
// matrices: m0 = rows n0..7 @ k0, m1 = rows n0..7 @ k8, m2 = rows n8..15 @ k0,
// m3 = rows n8..15 @ k8  ->  regs (b0,b1) frag0, (b2,b3) frag1.
__device__ __forceinline__ uint32_t ldm_off_b(int lane, int stride_halfs) {
    int r = lane & 7;
    int m = lane >> 3;                     // 0..3
    return (uint32_t)(((m >> 1) * 8 + r) * stride_halfs * 2 + (m & 1) * 16);
}

// ---------------------------------------------------------------------------
// LayerNorm: fp32 math, half output
// ---------------------------------------------------------------------------
__global__ void ln_kernel(const float* __restrict__ x) {
    int row = blockIdx.x;
    int t = threadIdx.x;
    float4 v = ((const float4*)(x + (size_t)row * DD))[t];
    float s  = v.x + v.y + v.z + v.w;
    float s2 = v.x*v.x + v.y*v.y + v.z*v.z + v.w*v.w;
#pragma unroll
    for (int o = 16; o > 0; o >>= 1) {
        s  += __shfl_xor_sync(0xffffffffu, s,  o);
        s2 += __shfl_xor_sync(0xffffffffu, s2, o);
    }
    __shared__ float sh[8];
    if ((t & 31) == 0) { sh[t >> 5] = s; sh[4 + (t >> 5)] = s2; }
    __syncthreads();
    s  = sh[0] + sh[1] + sh[2] + sh[3];
    s2 = sh[4] + sh[5] + sh[6] + sh[7];
    float mu  = s * (1.0f / DD);
    float var = fmaxf(s2 * (1.0f / DD) - mu * mu, 0.0f);
    float r   = rsqrtf(var + 1e-6f);
    __half2 h0 = __floats2half2_rn((v.x - mu) * r, (v.y - mu) * r);
    __half2 h1 = __floats2half2_rn((v.z - mu) * r, (v.w - mu) * r);
    ((__half2*)(g_xnh + (size_t)row * DD))[2 * t]     = h0;
    ((__half2*)(g_xnh + (size_t)row * DD))[2 * t + 1] = h1;
}

// Gated LN: o_input = u * layernorm(attn), half output into g_xnh
__global__ void gated_ln_kernel() {
    int row = blockIdx.x;
    int t = threadIdx.x;
    float4 v = ((const float4*)(g_at + (size_t)row * DD))[t];
    float s  = v.x + v.y + v.z + v.w;
    float s2 = v.x*v.x + v.y*v.y + v.z*v.z + v.w*v.w;
#pragma unroll
    for (int o = 16; o > 0; o >>= 1) {
        s  += __shfl_xor_sync(0xffffffffu, s,  o);
        s2 += __shfl_xor_sync(0xffffffffu, s2, o);
    }
    __shared__ float sh[8];
    if ((t & 31) == 0) { sh[t >> 5] = s; sh[4 + (t >> 5)] = s2; }
    __syncthreads();
    s  = sh[0] + sh[1] + sh[2] + sh[3];
    s2 = sh[4] + sh[5] + sh[6] + sh[7];
    float mu  = s * (1.0f / DD);
    float var = fmaxf(s2 * (1.0f / DD) - mu * mu, 0.0f);
    float r   = rsqrtf(var + 1e-6f);
    __half2 u01 = ((const __half2*)(g_mmh + (size_t)row * NC))[2 * t];
    __half2 u23 = ((const __half2*)(g_mmh + (size_t)row * NC))[2 * t + 1];
    float2 u0 = __half22float2(u01), u1 = __half22float2(u23);
    __half2 h0 = __floats2half2_rn(u0.x * (v.x - mu) * r, u0.y * (v.y - mu) * r);
    __half2 h1 = __floats2half2_rn(u1.x * (v.z - mu) * r, u1.y * (v.w - mu) * r);
    ((__half2*)(g_xnh + (size_t)row * DD))[2 * t]     = h0;
    ((__half2*)(g_xnh + (size_t)row * DD))[2 * t + 1] = h1;
}

// ---------------------------------------------------------------------------
// Weight converts (once per launch)
// ---------------------------------------------------------------------------
__global__ void cvt_w_t(const float* __restrict__ W) {
    __shared__ float tbuf[32][33];
    int lx = threadIdx.x & 31, ly = threadIdx.x >> 5;  // 32x8
    int bx = blockIdx.x, by = blockIdx.y;
    int col = bx * 32 + lx;
#pragma unroll
    for (int i = 0; i < 32; i += 8)
        tbuf[ly + i][lx] = W[(size_t)(by * 32 + ly + i) * NC + col];
    __syncthreads();
    int ok = by * 32 + lx;
#pragma unroll
    for (int i = 0; i < 32; i += 8)
        g_wh[(size_t)(bx * 32 + ly + i) * DD + ok] = __float2half_rn(tbuf[lx][ly + i]);
}

__global__ void cvt_ow(const float* __restrict__ W) {
    int i = blockIdx.x * 256 + threadIdx.x;
    float4 v = ((const float4*)W)[i];
    __half2 h0 = __floats2half2_rn(v.x, v.y);
    __half2 h1 = __floats2half2_rn(v.z, v.w);
    ((__half2*)g_owh)[2 * i]     = h0;
    ((__half2*)g_owh)[2 * i + 1] = h1;
}

// ---------------------------------------------------------------------------
// fp16 mma GEMM. Block tile 128x128, BK=64 halfs, 8 warps (2m x 4n),
// warp tile 64x32, cp.async double buffer. A [m][k], B [n][k] half.
// B-fragments via ldmatrix.x4 (non-trans) -- 2 per k-step instead of 16 LDS.
// ---------------------------------------------------------------------------
#define SAH   72
#define ASBH  (128 * SAH * 2)
#define GSMEMH (4 * ASBH)

template <int MODE>
__global__ __launch_bounds__(256)
void gemm_h(const __half* __restrict__ A, const __half* __restrict__ Bm,
            __half* __restrict__ Ch, float* __restrict__ Cf,
            const float* __restrict__ bias, const float* __restrict__ xres,
            int Nn, int K) {
    extern __shared__ char smem[];
    uint32_t sAu = smem_u32(smem);
    uint32_t sBu = sAu + 2 * ASBH;

    int tid = threadIdx.x;
    int wid = tid >> 5, lane = tid & 31;
    int m0 = blockIdx.y * 128, n0 = blockIdx.x * 128;
    int wm = (wid & 1) * 64;
    int wn = (wid >> 1) * 32;

    float acc[4][4][4];
#pragma unroll
    for (int i = 0; i < 4; i++)
#pragma unroll
        for (int j = 0; j < 4; j++)
#pragma unroll
            for (int r = 0; r < 4; r++) acc[i][j][r] = 0.0f;

    const int NCH = K / 64;
    uint32_t aoff = ldm_off_h(lane, SAH);
    uint32_t boff = (uint32_t)(wn * SAH * 2) + ldm_off_b(lane, SAH);

    auto stageA = [&](int c, int s) {
#pragma unroll
        for (int i = 0; i < 4; i++) {
            int idx = tid + i * 256;
            int row = idx >> 3, seg = idx & 7;
            cp16(sAu + s * ASBH + (row * SAH + seg * 8) * 2,
                 A + (size_t)(m0 + row) * K + c * 64 + seg * 8);
        }
    };
    auto stageB = [&](int c, int s) {
#pragma unroll
        for (int i = 0; i < 4; i++) {
            int idx = tid + i * 256;
            int row = idx >> 3, seg = idx & 7;
            cp16(sBu + s * ASBH + (row * SAH + seg * 8) * 2,
                 Bm + (size_t)(n0 + row) * K + c * 64 + seg * 8);
        }
    };

    stageA(0, 0); stageB(0, 0); CP_COMMIT();

    for (int c = 0; c < NCH; c++) {
        int s = c & 1;
        if (c + 1 < NCH) {
            stageA(c + 1, s ^ 1); stageB(c + 1, s ^ 1); CP_COMMIT();
            CP_WAIT(1);
        } else {
            CP_WAIT(0);
        }
        __syncthreads();

#pragma unroll
        for (int ks = 0; ks < 4; ks++) {      // 4 k16 steps per 64-chunk
            uint32_t b01[4], b23[4];
            ldmA(b01, sBu + s * ASBH + boff + ks * 32);
            ldmA(b23, sBu + s * ASBH + boff + 16 * SAH * 2 + ks * 32);
#pragma unroll
            for (int im = 0; im < 4; im++) {
                uint32_t a[4];
                ldmA(a, sAu + s * ASBH + (uint32_t)((wm + im * 16) * SAH * 2 + ks * 32) + aoff);
                mma_f16(acc[im][0], a, b01[0], b01[1]);
                mma_f16(acc[im][1], a, b01[2], b01[3]);
                mma_f16(acc[im][2], a, b23[0], b23[1]);
                mma_f16(acc[im][3], a, b23[2], b23[3]);
            }
        }
        __syncthreads();
    }

    int er = lane >> 2, ec = (lane & 3) * 2;
#pragma unroll
    for (int im = 0; im < 4; im++) {
#pragma unroll
        for (int in = 0; in < 4; in++) {
            int row = m0 + wm + im * 16 + er;
            int col = n0 + wn + in * 8 + ec;
#pragma unroll
            for (int h = 0; h < 2; h++) {
                float v0 = acc[im][in][2 * h + 0];
                float v1 = acc[im][in][2 * h + 1];
                int rr = row + 8 * h;
                if (MODE == 0) {
                    __half2 o = __floats2half2_rn(silu_f(v0), silu_f(v1));
                    *(__half2*)(Ch + (size_t)rr * Nn + col) = o;
                } else {
                    float2 bi = *(const float2*)(bias + col);
                    float2 xr = *(const float2*)(xres + (size_t)rr * Nn + col);
                    float2 o; o.x = v0 + bi.x + xr.x; o.y = v1 + bi.y + xr.y;
                    *(float2*)(Cf + (size_t)rr * Nn + col) = o;
                }
            }
        }
    }
}

// ---------------------------------------------------------------------------
// Fused causal silu-attention, fp16 mma. 64x64 tiles, 8 warps (2m x 4n).
// K B-frags now via ldmatrix.x4 non-trans (1 per k-step instead of 8 LDS);
// V B-frags via ldmatrix.x4.trans. cp.async double-buffered K/V.
// ---------------------------------------------------------------------------
#define SATH  72
#define ATILEH (64 * SATH * 2)            // 9216
#define HOFF_K ATILEH
#define HOFF_V (3 * ATILEH)
#define HOFF_S (5 * ATILEH)
#define ASMEMH (6 * ATILEH)               // 55296

__global__ __launch_bounds__(256)
void attn_mma() {
    extern __shared__ char smem[];
    __half* Ss = (__half*)(smem + HOFF_S);
    uint32_t sbase = smem_u32(smem);
    uint32_t Qsu = sbase;
    uint32_t Ssu = sbase + HOFF_S;

    int qt = blockIdx.x, h = blockIdx.y, b = blockIdx.z;
    int tid = threadIdx.x;
    int wid = tid >> 5, lane = tid & 31;
    int wm = (wid & 1) * 32;
    int wn = (wid >> 1) * 16;
    const int qcol = 1024 + h * HD;
    const int kcol = 1536 + h * HD;
    const int vcol = 512 + h * HD;
    uint32_t aoff = ldm_off_h(lane, SATH);
    uint32_t koff = (uint32_t)(wn * SATH * 2) + ldm_off_b(lane, SATH);

    // V ldmatrix.x4.trans per-lane address pieces
    int tl = lane & 7;
    int tmi = lane >> 3;
    int tkr = (tmi & 1) * 8 + tl;
    int tnc = (tmi >> 1) * 8;

    auto stageQ = [&]() {
#pragma unroll
        for (int i = 0; i < 2; i++) {
            int idx = tid + i * 256;
            int row = idx >> 3, seg = idx & 7;
            cp16(Qsu + (row * SATH + seg * 8) * 2,
                 g_mmh + (size_t)(b * NN + qt * 64 + row) * NC + qcol + seg * 8);
        }
    };
    auto stageKV = [&](int kt, int s) {
        uint32_t kd = sbase + HOFF_K + s * ATILEH;
        uint32_t vd = sbase + HOFF_V + s * ATILEH;
#pragma unroll
        for (int i = 0; i < 2; i++) {
            int idx = tid + i * 256;
            int row = idx >> 3, seg = idx & 7;
            size_t gb = (size_t)(b * NN + kt * 64 + row) * NC;
            uint32_t so = (uint32_t)((row * SATH + seg * 8) * 2);
            cp16(kd + so, g_mmh + gb + kcol + seg * 8);
            cp16(vd + so, g_mmh + gb + vcol + seg * 8);
        }
    };

    float oacc[2][2][4];
#pragma unroll
    for (int i = 0; i < 2; i++)
#pragma unroll
        for (int j = 0; j < 2; j++)
#pragma unroll
            for (int r = 0; r < 4; r++) oacc[i][j][r] = 0.0f;

    const float inv_n = 1.0f / (float)NN;
    int er = lane >> 2, ec = (lane & 3) * 2;
    const int nkt = qt + 1;

    stageQ(); stageKV(0, 0); CP_COMMIT();

    for (int kt = 0; kt < nkt; kt++) {
        int s = kt & 1;
        CP_WAIT(0);
        __syncthreads();   // tile kt visible; all warps past phase2 of kt-1

        if (kt + 1 < nkt) { stageKV(kt + 1, s ^ 1); CP_COMMIT(); }

        uint32_t Ksu = sbase + HOFF_K + s * ATILEH;
        uint32_t Vsu = sbase + HOFF_V + s * ATILEH;

        // Phase 1: S = Q @ K^T  (K B-frags via ldmatrix.x4 non-trans)
        float sacc[2][2][4];
#pragma unroll
        for (int i = 0; i < 2; i++)
#pragma unroll
            for (int j = 0; j < 2; j++)
#pragma unroll
                for (int r = 0; r < 4; r++) sacc[i][j][r] = 0.0f;
#pragma unroll
        for (int ks = 0; ks < 4; ks++) {
            uint32_t bk[4];
            ldmA(bk, Ksu + koff + ks * 32);
#pragma unroll
            for (int im = 0; im < 2; im++) {
                uint32_t a[4];
                ldmA(a, Qsu + (uint32_t)((wm + im * 16) * SATH * 2 + ks * 32) + aoff);
                mma_f16(sacc[im][0], a, bk[0], bk[1]);
                mma_f16(sacc[im][1], a, bk[2], bk[3]);
            }
        }

        // silu + causal mask -> Ss (half). inv_n deferred to O epilogue.
        bool diag = (kt == qt);
#pragma unroll
        for (int im = 0; im < 2; im++) {
#pragma unroll
            for (int in = 0; in < 2; in++) {
#pragma unroll
                for (int hh = 0; hh < 2; hh++) {
                    int i = wm + im * 16 + er + 8 * hh;
                    int j = wn + in * 8 + ec;
                    float v0 = silu_f(sacc[im][in][2 * hh + 0]);
                    float v1 = silu_f(sacc[im][in][2 * hh + 1]);
                    if (diag) {
                        if (j > i) v0 = 0.0f;
                        if (j + 1 > i) v1 = 0.0f;
                    }
                    *(__half2*)(Ss + i * SATH + j) = __floats2half2_rn(v0, v1);
                }
            }
        }
        __syncthreads();   // Ss visible

        // Phase 2: O += S @ V  (V B-frags via ldmatrix.x4.trans)
#pragma unroll
        for (int ks = 0; ks < 4; ks++) {
            uint32_t bv[4];
            ldmT(bv, Vsu + (uint32_t)(((ks * 16 + tkr) * SATH + wn + tnc) * 2));
#pragma unroll
            for (int im = 0; im < 2; im++) {
                uint32_t a[4];
                ldmA(a, Ssu + (uint32_t)((wm + im * 16) * SATH * 2 + ks * 32) + aoff);
                mma_f16(oacc[im][0], a, bv[0], bv[1]);
                mma_f16(oacc[im][1], a, bv[2], bv[3]);
            }
        }
    }

    // Write O tile (scaled by 1/N)
#pragma unroll
    for (int im = 0; im < 2; im++) {
#pragma unroll
        for (int in = 0; in < 2; in++) {
#pragma unroll
            for (int hh = 0; hh < 2; hh++) {
                int n = qt * 64 + wm + im * 16 + er + 8 * hh;
                int j = h * HD + wn + in * 8 + ec;
                float2 o;
                o.x = oacc[im][in][2 * hh + 0] * inv_n;
                o.y = oacc[im][in][2 * hh + 1] * inv_n;
                *(float2*)(g_at + (size_t)(b * NN + n) * DD + j) = o;
            }
        }
    }
}

// ---------------------------------------------------------------------------
extern "C" void kernel_launch(void* const* d_in, const int* in_sizes, int n_in,
                              void* d_out, int out_size) {
    const float* x    = (const float*)d_in[0];
    const float* uvqk = (const float*)d_in[2];
    const float* ow   = (const float*)d_in[3];
    const float* ob   = (const float*)d_in[4];
    float* out = (float*)d_out;

    void *pxnh, *pmmh, *pwh, *powh;
    cudaGetSymbolAddress(&pxnh, g_xnh);
    cudaGetSymbolAddress(&pmmh, g_mmh);
    cudaGetSymbolAddress(&pwh,  g_wh);
    cudaGetSymbolAddress(&powh, g_owh);

    cudaFuncSetAttribute(gemm_h<0>, cudaFuncAttributeMaxDynamicSharedMemorySize, GSMEMH);
    cudaFuncSetAttribute(gemm_h<1>, cudaFuncAttributeMaxDynamicSharedMemorySize, GSMEMH);
    cudaFuncSetAttribute(attn_mma, cudaFuncAttributeMaxDynamicSharedMemorySize, ASMEMH);

    // 0. weight converts
    cvt_w_t<<<dim3(NC / 32, DD / 32), 256>>>(uvqk);
    cvt_ow<<<DD * DD / 1024, 256>>>(ow);
    // 1. xn = layernorm(x) -> half
    ln_kernel<<<RR, 128>>>(x);
    // 2. mm = silu(xn @ uvqk) -> half
    gemm_h<0><<<dim3(NC / 128, RR / 128), 256, GSMEMH>>>(
        (const __half*)pxnh, (const __half*)pwh, (__half*)pmmh, nullptr,
        nullptr, nullptr, NC, DD);
    // 3. attention
    attn_mma<<<dim3(NN / 64, HH, BB), 256, ASMEMH>>>();
    // 4. o_input = u * layernorm(attn) -> half
    gated_ln_kernel<<<RR, 128>>>();
    // 5. out = o_input @ o_weight^T + bias + x -> fp32
    gemm_h<1><<<dim3(DD / 128, RR / 128), 256, GSMEMH>>>(
        (const __half*)pxnh, (const __half*)powh, nullptr, out, ob, x, DD, DD);
}